// round 1
// baseline (speedup 1.0000x reference)
#include <cuda_runtime.h>
#include <cuda_bf16.h>

#define FULL 0xffffffffu
#define EPS 1e-8f
#define WARPS_PER_BLOCK 8
#define THREADS (WARPS_PER_BLOCK * 32)

__device__ __forceinline__ float fast_sqrt(float x) {
    float r;
    asm("sqrt.approx.ftz.f32 %0, %1;" : "=f"(r) : "f"(x));
    return r;
}

__global__ __launch_bounds__(THREADS)
void gib_kernel(const float* __restrict__ points,
                const float* __restrict__ q_coords,
                const int*   __restrict__ support_idxs,
                const float* __restrict__ cy_radius,
                const float* __restrict__ disk_radius,
                const float* __restrict__ disk_width,
                const float* __restrict__ cone_radius,
                const float* __restrict__ cone_inc,
                const float* __restrict__ ellip_radii,
                const float* __restrict__ lambdas,
                float* __restrict__ out,
                int M)
{
    // Per-weight-slot coefficients: w = exp(a*x2 + b*y2 + c*z2 + e*(rxy - inc*z)^2)
    __shared__ float4 s_coef[32];
    __shared__ float  s_inc[32];
    __shared__ float  s_lam[32 * 16];               // lambdas pre-scaled by 1/K
    __shared__ float  s_acc[WARPS_PER_BLOCK][32];

    int tid = threadIdx.x;

    if (tid < 32) {
        int kind = tid >> 3;
        int g    = tid & 7;
        float a = 0.f, b = 0.f, c = 0.f, e = 0.f, inc = 0.f;
        if (kind == 0) {                 // cylinder
            float r = cy_radius[g];
            float v = -0.5f / (r * r + EPS);
            a = v; b = v;
        } else if (kind == 1) {          // cone
            float r = cone_radius[g];
            e = -0.5f / (r * r + EPS);
            inc = cone_inc[g];
        } else if (kind == 2) {          // disk
            float r = disk_radius[g];
            float w = disk_width[g];
            float v = -0.5f / (r * r + EPS);
            a = v; b = v;
            c = -0.5f / (w * w + EPS);
        } else {                         // ellipsoid
            float ex = ellip_radii[g * 3 + 0];
            float ey = ellip_radii[g * 3 + 1];
            float ez = ellip_radii[g * 3 + 2];
            a = -0.5f / (ex * ex + EPS);
            b = -0.5f / (ey * ey + EPS);
            c = -0.5f / (ez * ez + EPS);
        }
        s_coef[tid] = make_float4(a, b, c, e);
        s_inc[tid] = inc;
    }
    for (int i = tid; i < 32 * 16; i += THREADS)
        s_lam[i] = lambdas[i] * (1.0f / 32.0f);     // fold masked-mean 1/K
    __syncthreads();

    int lane = tid & 31;
    int wid  = tid >> 5;
    int m = blockIdx.x * WARPS_PER_BLOCK + wid;
    if (m < M) {
        float4 cf = s_coef[lane];
        float  inc = s_inc[lane];

        // Phase 1: lane k gathers its support point, computes rel + mask
        float qx = q_coords[3 * m + 0];
        float qy = q_coords[3 * m + 1];
        float qz = q_coords[3 * m + 2];
        int id = support_idxs[m * 32 + lane];
        float px = points[3 * id + 0];
        float py = points[3 * id + 1];
        float pz = points[3 * id + 2];
        float x = px - qx, y = py - qy, z = pz - qz;
        float x2 = x * x, y2 = y * y, z2 = z * z;
        float xy2 = x2 + y2;
        float d2  = xy2 + z2;
        float rxy = fast_sqrt(xy2 + EPS);

        unsigned surv = __ballot_sync(FULL, d2 <= 1.0f);

        // Phase 2: loop survivors; lane l computes weight-slot l for each
        float acc = 0.0f;
        while (surv) {
            int s = __ffs(surv) - 1;
            surv &= surv - 1;
            float sx2  = __shfl_sync(FULL, x2,  s);
            float sy2  = __shfl_sync(FULL, y2,  s);
            float sz   = __shfl_sync(FULL, z,   s);
            float srxy = __shfl_sync(FULL, rxy, s);
            float sz2 = sz * sz;
            float dd  = fmaf(-inc, sz, srxy);
            float t = fmaf(cf.x, sx2,
                      fmaf(cf.y, sy2,
                      fmaf(cf.z, sz2, (cf.w * dd) * dd)));
            acc += __expf(t);
        }

        // Epilogue: stage 32 per-slot sums, 16 lanes do (32)x(32,16) projection
        s_acc[wid][lane] = acc;
        __syncwarp();
        if (lane < 16) {
            float o = 0.0f;
            #pragma unroll
            for (int j = 0; j < 32; j++)
                o = fmaf(s_acc[wid][j], s_lam[j * 16 + lane], o);
            out[m * 16 + lane] = o;
        }
    }
}

extern "C" void kernel_launch(void* const* d_in, const int* in_sizes, int n_in,
                              void* d_out, int out_size) {
    const float* points       = (const float*)d_in[0];
    const float* q_coords     = (const float*)d_in[1];
    const int*   support_idxs = (const int*)  d_in[2];
    const float* cy_radius    = (const float*)d_in[3];
    const float* disk_radius  = (const float*)d_in[4];
    const float* disk_width   = (const float*)d_in[5];
    const float* cone_radius  = (const float*)d_in[6];
    const float* cone_inc     = (const float*)d_in[7];
    const float* ellip_radii  = (const float*)d_in[8];
    const float* lambdas      = (const float*)d_in[9];
    float* out = (float*)d_out;

    int M = in_sizes[1] / 3;   // q_coords has M*3 elements
    int blocks = (M + WARPS_PER_BLOCK - 1) / WARPS_PER_BLOCK;
    gib_kernel<<<blocks, THREADS>>>(points, q_coords, support_idxs,
                                    cy_radius, disk_radius, disk_width,
                                    cone_radius, cone_inc, ellip_radii,
                                    lambdas, out, M);
}

// round 2
// speedup vs baseline: 1.0849x; 1.0849x over previous
#include <cuda_runtime.h>
#include <cuda_bf16.h>

#define FULL 0xffffffffu
#define EPS 1e-8f
#define WARPS_PER_BLOCK 8
#define THREADS (WARPS_PER_BLOCK * 32)
#define N_MAX 100000

// Packed points scratch: (x, y, z, 0) per point — single LDG.128 gather.
__device__ float4 g_points4[N_MAX];

__device__ __forceinline__ float fast_sqrt(float x) {
    float r;
    asm("sqrt.approx.ftz.f32 %0, %1;" : "=f"(r) : "f"(x));
    return r;
}

__global__ void pack_points_kernel(const float* __restrict__ points, int N) {
    int i = blockIdx.x * blockDim.x + threadIdx.x;
    if (i < N) {
        g_points4[i] = make_float4(points[3 * i + 0],
                                   points[3 * i + 1],
                                   points[3 * i + 2], 0.0f);
    }
}

__global__ __launch_bounds__(THREADS)
void gib_kernel(const float* __restrict__ q_coords,
                const int*   __restrict__ support_idxs,
                const float* __restrict__ cy_radius,
                const float* __restrict__ disk_radius,
                const float* __restrict__ disk_width,
                const float* __restrict__ cone_radius,
                const float* __restrict__ cone_inc,
                const float* __restrict__ ellip_radii,
                const float* __restrict__ lambdas,
                float* __restrict__ out,
                int M)
{
    // Per-weight-slot coefficients: w = exp(a*x2 + b*y2 + c*z2 + e*(rxy - inc*z)^2)
    __shared__ float4 s_coef[32];
    __shared__ float  s_inc[32];
    __shared__ float  s_lam[32 * 16];               // lambdas pre-scaled by 1/K
    __shared__ float  s_acc[WARPS_PER_BLOCK][32];

    int tid = threadIdx.x;

    if (tid < 32) {
        int kind = tid >> 3;
        int g    = tid & 7;
        float a = 0.f, b = 0.f, c = 0.f, e = 0.f, inc = 0.f;
        if (kind == 0) {                 // cylinder
            float r = cy_radius[g];
            float v = -0.5f / (r * r + EPS);
            a = v; b = v;
        } else if (kind == 1) {          // cone
            float r = cone_radius[g];
            e = -0.5f / (r * r + EPS);
            inc = cone_inc[g];
        } else if (kind == 2) {          // disk
            float r = disk_radius[g];
            float w = disk_width[g];
            float v = -0.5f / (r * r + EPS);
            a = v; b = v;
            c = -0.5f / (w * w + EPS);
        } else {                         // ellipsoid
            float ex = ellip_radii[g * 3 + 0];
            float ey = ellip_radii[g * 3 + 1];
            float ez = ellip_radii[g * 3 + 2];
            a = -0.5f / (ex * ex + EPS);
            b = -0.5f / (ey * ey + EPS);
            c = -0.5f / (ez * ez + EPS);
        }
        s_coef[tid] = make_float4(a, b, c, e);
        s_inc[tid] = inc;
    }
    for (int i = tid; i < 32 * 16; i += THREADS)
        s_lam[i] = lambdas[i] * (1.0f / 32.0f);     // fold masked-mean 1/K
    __syncthreads();

    int lane = tid & 31;
    int wid  = tid >> 5;
    int m = blockIdx.x * WARPS_PER_BLOCK + wid;
    if (m < M) {
        float4 cf = s_coef[lane];
        float  inc = s_inc[lane];

        // Phase 1: lane k gathers its support point (1x LDG.128), rel + mask
        float qx = q_coords[3 * m + 0];
        float qy = q_coords[3 * m + 1];
        float qz = q_coords[3 * m + 2];
        int id = support_idxs[m * 32 + lane];
        float4 p = g_points4[id];
        float x = p.x - qx, y = p.y - qy, z = p.z - qz;
        float x2 = x * x, y2 = y * y, z2 = z * z;
        float xy2 = x2 + y2;
        float d2  = xy2 + z2;
        float rxy = fast_sqrt(xy2 + EPS);

        unsigned surv = __ballot_sync(FULL, d2 <= 1.0f);

        // Phase 2: loop survivors; lane l computes weight-slot l for each
        float acc = 0.0f;
        while (surv) {
            int s = __ffs(surv) - 1;
            surv &= surv - 1;
            float sx2  = __shfl_sync(FULL, x2,  s);
            float sy2  = __shfl_sync(FULL, y2,  s);
            float sz   = __shfl_sync(FULL, z,   s);
            float srxy = __shfl_sync(FULL, rxy, s);
            float sz2 = sz * sz;
            float dd  = fmaf(-inc, sz, srxy);
            float t = fmaf(cf.x, sx2,
                      fmaf(cf.y, sy2,
                      fmaf(cf.z, sz2, (cf.w * dd) * dd)));
            acc += __expf(t);
        }

        // Epilogue: stage 32 per-slot sums, 16 lanes do (32)x(32,16) projection
        s_acc[wid][lane] = acc;
        __syncwarp();
        if (lane < 16) {
            float o = 0.0f;
            #pragma unroll
            for (int j = 0; j < 32; j++)
                o = fmaf(s_acc[wid][j], s_lam[j * 16 + lane], o);
            out[m * 16 + lane] = o;
        }
    }
}

extern "C" void kernel_launch(void* const* d_in, const int* in_sizes, int n_in,
                              void* d_out, int out_size) {
    const float* points       = (const float*)d_in[0];
    const float* q_coords     = (const float*)d_in[1];
    const int*   support_idxs = (const int*)  d_in[2];
    const float* cy_radius    = (const float*)d_in[3];
    const float* disk_radius  = (const float*)d_in[4];
    const float* disk_width   = (const float*)d_in[5];
    const float* cone_radius  = (const float*)d_in[6];
    const float* cone_inc     = (const float*)d_in[7];
    const float* ellip_radii  = (const float*)d_in[8];
    const float* lambdas      = (const float*)d_in[9];
    float* out = (float*)d_out;

    int N = in_sizes[0] / 3;   // points has N*3 elements
    int M = in_sizes[1] / 3;   // q_coords has M*3 elements

    pack_points_kernel<<<(N + 255) / 256, 256>>>(points, N);

    int blocks = (M + WARPS_PER_BLOCK - 1) / WARPS_PER_BLOCK;
    gib_kernel<<<blocks, THREADS>>>(q_coords, support_idxs,
                                    cy_radius, disk_radius, disk_width,
                                    cone_radius, cone_inc, ellip_radii,
                                    lambdas, out, M);
}

// round 3
// speedup vs baseline: 1.2796x; 1.1794x over previous
#include <cuda_runtime.h>
#include <cuda_bf16.h>

#define FULL 0xffffffffu
#define EPS 1e-8f
#define WARPS_PER_BLOCK 8
#define THREADS (WARPS_PER_BLOCK * 32)
#define Q_PER_BLOCK (WARPS_PER_BLOCK * 2)
#define N_MAX 100000

// Packed points scratch: (x, y, z, 0) per point — single LDG.128 gather.
__device__ float4 g_points4[N_MAX];

__device__ __forceinline__ float fast_sqrt(float x) {
    float r;
    asm("sqrt.approx.ftz.f32 %0, %1;" : "=f"(r) : "f"(x));
    return r;
}

__global__ void pack_points_kernel(const float* __restrict__ points, int N) {
    int i = blockIdx.x * blockDim.x + threadIdx.x;
    if (i < N) {
        g_points4[i] = make_float4(points[3 * i + 0],
                                   points[3 * i + 1],
                                   points[3 * i + 2], 0.0f);
    }
}

__global__ __launch_bounds__(THREADS)
void gib_kernel(const float* __restrict__ q_coords,
                const int*   __restrict__ support_idxs,
                const float* __restrict__ cy_radius,
                const float* __restrict__ disk_radius,
                const float* __restrict__ disk_width,
                const float* __restrict__ cone_radius,
                const float* __restrict__ cone_inc,
                const float* __restrict__ ellip_radii,
                const float* __restrict__ lambdas,
                float* __restrict__ out,
                int M)
{
    // Per-slot coefficients: w = exp(a*x2 + b*y2 + c*z2 + e*(rxy - inc*z)^2)
    __shared__ float4 s_coef[32];
    __shared__ float  s_inc[32];
    __shared__ float  s_lamT[16][36];                // transposed, padded, /K folded
    __shared__ float  s_acc[WARPS_PER_BLOCK][2][32];

    int tid = threadIdx.x;

    if (tid < 32) {
        int kind = tid >> 3;
        int g    = tid & 7;
        float a = 0.f, b = 0.f, c = 0.f, e = 0.f, inc = 0.f;
        if (kind == 0) {                 // cylinder
            float r = cy_radius[g];
            float v = -0.5f / (r * r + EPS);
            a = v; b = v;
        } else if (kind == 1) {          // cone
            float r = cone_radius[g];
            e = -0.5f / (r * r + EPS);
            inc = cone_inc[g];
        } else if (kind == 2) {          // disk
            float r = disk_radius[g];
            float w = disk_width[g];
            float v = -0.5f / (r * r + EPS);
            a = v; b = v;
            c = -0.5f / (w * w + EPS);
        } else {                         // ellipsoid
            float ex = ellip_radii[g * 3 + 0];
            float ey = ellip_radii[g * 3 + 1];
            float ez = ellip_radii[g * 3 + 2];
            a = -0.5f / (ex * ex + EPS);
            b = -0.5f / (ey * ey + EPS);
            c = -0.5f / (ez * ez + EPS);
        }
        s_coef[tid] = make_float4(a, b, c, e);
        s_inc[tid] = inc;
    }
    for (int i = tid; i < 32 * 16; i += THREADS) {
        int j = i >> 4, o = i & 15;
        s_lamT[o][j] = lambdas[i] * (1.0f / 32.0f);  // fold masked-mean 1/K
    }
    __syncthreads();

    int lane = tid & 31;
    int wid  = tid >> 5;
    int m0 = blockIdx.x * Q_PER_BLOCK + 2 * wid;
    int m1 = m0 + 1;

    float4 cf = s_coef[lane];
    float  inc = s_inc[lane];

    float x2a = 0.f, y2a = 0.f, za = 0.f, rxya = 0.f, d2a = 1e9f;
    float x2b = 0.f, y2b = 0.f, zb = 0.f, rxyb = 0.f, d2b = 1e9f;

    if (m0 < M) {
        // Issue both gathers up front (MLP=2 per warp)
        int ida = __ldg(&support_idxs[m0 * 32 + lane]);
        int idb = (m1 < M) ? __ldg(&support_idxs[m1 * 32 + lane]) : ida;
        float4 pa = g_points4[ida];
        float4 pb = g_points4[idb];

        float qxa = q_coords[3 * m0 + 0];
        float qya = q_coords[3 * m0 + 1];
        float qza = q_coords[3 * m0 + 2];
        int mq = (m1 < M) ? m1 : m0;
        float qxb = q_coords[3 * mq + 0];
        float qyb = q_coords[3 * mq + 1];
        float qzb = q_coords[3 * mq + 2];

        float xa = pa.x - qxa, ya = pa.y - qya; za = pa.z - qza;
        float xb = pb.x - qxb, yb = pb.y - qyb; zb = pb.z - qzb;
        x2a = xa * xa; y2a = ya * ya;
        x2b = xb * xb; y2b = yb * yb;
        float xy2a = x2a + y2a, xy2b = x2b + y2b;
        d2a = xy2a + za * za;
        d2b = xy2b + zb * zb;
        rxya = fast_sqrt(xy2a + EPS);
        rxyb = fast_sqrt(xy2b + EPS);
    }

    unsigned surv0 = __ballot_sync(FULL, d2a <= 1.0f);
    unsigned surv1 = __ballot_sync(FULL, (d2b <= 1.0f) && (m1 < M));

    // Fused survivor loop: surv0/surv1 are warp-uniform -> no divergence,
    // two independent shuffle->exp chains give 2x ILP.
    float acc0 = 0.0f, acc1 = 0.0f;
    while (surv0 | surv1) {
        if (surv0) {
            int s = __ffs(surv0) - 1;
            surv0 &= surv0 - 1;
            float sx2  = __shfl_sync(FULL, x2a,  s);
            float sy2  = __shfl_sync(FULL, y2a,  s);
            float sz   = __shfl_sync(FULL, za,   s);
            float srxy = __shfl_sync(FULL, rxya, s);
            float dd = fmaf(-inc, sz, srxy);
            float t = fmaf(cf.x, sx2,
                      fmaf(cf.y, sy2,
                      fmaf(cf.z, sz * sz, (cf.w * dd) * dd)));
            acc0 += __expf(t);
        }
        if (surv1) {
            int s = __ffs(surv1) - 1;
            surv1 &= surv1 - 1;
            float sx2  = __shfl_sync(FULL, x2b,  s);
            float sy2  = __shfl_sync(FULL, y2b,  s);
            float sz   = __shfl_sync(FULL, zb,   s);
            float srxy = __shfl_sync(FULL, rxyb, s);
            float dd = fmaf(-inc, sz, srxy);
            float t = fmaf(cf.x, sx2,
                      fmaf(cf.y, sy2,
                      fmaf(cf.z, sz * sz, (cf.w * dd) * dd)));
            acc1 += __expf(t);
        }
    }

    // Epilogue: full warp. Lanes 0-15 project query m0, lanes 16-31 query m1.
    s_acc[wid][0][lane] = acc0;
    s_acc[wid][1][lane] = acc1;
    __syncwarp();

    int qsel = lane >> 4;
    int o    = lane & 15;
    int m    = qsel ? m1 : m0;
    if (m < M) {
        const float* accp = s_acc[wid][qsel];
        float ot = 0.0f;
        #pragma unroll
        for (int j = 0; j < 32; j += 4) {
            float4 lam4 = *(const float4*)&s_lamT[o][j];
            float4 a4   = *(const float4*)&accp[j];
            ot = fmaf(a4.x, lam4.x,
                 fmaf(a4.y, lam4.y,
                 fmaf(a4.z, lam4.z,
                 fmaf(a4.w, lam4.w, ot))));
        }
        out[m * 16 + o] = ot;
    }
}

extern "C" void kernel_launch(void* const* d_in, const int* in_sizes, int n_in,
                              void* d_out, int out_size) {
    const float* points       = (const float*)d_in[0];
    const float* q_coords     = (const float*)d_in[1];
    const int*   support_idxs = (const int*)  d_in[2];
    const float* cy_radius    = (const float*)d_in[3];
    const float* disk_radius  = (const float*)d_in[4];
    const float* disk_width   = (const float*)d_in[5];
    const float* cone_radius  = (const float*)d_in[6];
    const float* cone_inc     = (const float*)d_in[7];
    const float* ellip_radii  = (const float*)d_in[8];
    const float* lambdas      = (const float*)d_in[9];
    float* out = (float*)d_out;

    int N = in_sizes[0] / 3;   // points has N*3 elements
    int M = in_sizes[1] / 3;   // q_coords has M*3 elements

    pack_points_kernel<<<(N + 255) / 256, 256>>>(points, N);

    int blocks = (M + Q_PER_BLOCK - 1) / Q_PER_BLOCK;
    gib_kernel<<<blocks, THREADS>>>(q_coords, support_idxs,
                                    cy_radius, disk_radius, disk_width,
                                    cone_radius, cone_inc, ellip_radii,
                                    lambdas, out, M);
}

// round 4
// speedup vs baseline: 1.3031x; 1.0184x over previous
#include <cuda_runtime.h>
#include <cuda_bf16.h>

#define FULL 0xffffffffu
#define EPS 1e-8f
#define WARPS_PER_BLOCK 8
#define THREADS (WARPS_PER_BLOCK * 32)
#define Q_PER_BLOCK (WARPS_PER_BLOCK * 2)
#define N_MAX 100000

// Packed points scratch: (x, y, z, 0) per point — single LDG.128 gather.
__device__ float4 g_points4[N_MAX];

__device__ __forceinline__ float fast_sqrt(float x) {
    float r;
    asm("sqrt.approx.ftz.f32 %0, %1;" : "=f"(r) : "f"(x));
    return r;
}

__global__ void pack_points_kernel(const float* __restrict__ points, int N) {
    int i = blockIdx.x * blockDim.x + threadIdx.x;
    if (i < N) {
        g_points4[i] = make_float4(points[3 * i + 0],
                                   points[3 * i + 1],
                                   points[3 * i + 2], 0.0f);
    }
}

__global__ __launch_bounds__(THREADS)
void gib_kernel(const float* __restrict__ q_coords,
                const int*   __restrict__ support_idxs,
                const float* __restrict__ cy_radius,
                const float* __restrict__ disk_radius,
                const float* __restrict__ disk_width,
                const float* __restrict__ cone_radius,
                const float* __restrict__ cone_inc,
                const float* __restrict__ ellip_radii,
                const float* __restrict__ lambdas,
                float* __restrict__ out,
                int M)
{
    // Per-slot coefficients: w = exp(a*x2 + b*y2 + c*z2 + e*(rxy - inc*z)^2)
    __shared__ float4 s_coef[32];
    __shared__ float  s_inc[32];
    __shared__ float  s_lamT[16][36];                 // transposed, padded, /K folded
    __shared__ float4 s_surv[WARPS_PER_BLOCK][2][32]; // compacted survivor data
    __shared__ float  s_acc[WARPS_PER_BLOCK][2][32];

    int tid = threadIdx.x;

    if (tid < 32) {
        int kind = tid >> 3;
        int g    = tid & 7;
        float a = 0.f, b = 0.f, c = 0.f, e = 0.f, inc = 0.f;
        if (kind == 0) {                 // cylinder
            float r = cy_radius[g];
            float v = -0.5f / (r * r + EPS);
            a = v; b = v;
        } else if (kind == 1) {          // cone
            float r = cone_radius[g];
            e = -0.5f / (r * r + EPS);
            inc = cone_inc[g];
        } else if (kind == 2) {          // disk
            float r = disk_radius[g];
            float w = disk_width[g];
            float v = -0.5f / (r * r + EPS);
            a = v; b = v;
            c = -0.5f / (w * w + EPS);
        } else {                         // ellipsoid
            float ex = ellip_radii[g * 3 + 0];
            float ey = ellip_radii[g * 3 + 1];
            float ez = ellip_radii[g * 3 + 2];
            a = -0.5f / (ex * ex + EPS);
            b = -0.5f / (ey * ey + EPS);
            c = -0.5f / (ez * ez + EPS);
        }
        s_coef[tid] = make_float4(a, b, c, e);
        s_inc[tid] = inc;
    }
    for (int i = tid; i < 32 * 16; i += THREADS) {
        int j = i >> 4, o = i & 15;
        s_lamT[o][j] = lambdas[i] * (1.0f / 32.0f);   // fold masked-mean 1/K
    }
    __syncthreads();

    int lane = tid & 31;
    int wid  = tid >> 5;
    int m0 = blockIdx.x * Q_PER_BLOCK + 2 * wid;
    int m1 = m0 + 1;

    float4 cf = s_coef[lane];
    float  inc = s_inc[lane];

    float x2a = 0.f, y2a = 0.f, za = 0.f, rxya = 0.f, d2a = 1e9f;
    float x2b = 0.f, y2b = 0.f, zb = 0.f, rxyb = 0.f, d2b = 1e9f;

    if (m0 < M) {
        // Issue both gathers up front (MLP=2 per warp)
        int ida = __ldg(&support_idxs[m0 * 32 + lane]);
        int idb = (m1 < M) ? __ldg(&support_idxs[m1 * 32 + lane]) : ida;
        float4 pa = g_points4[ida];
        float4 pb = g_points4[idb];

        float qxa = q_coords[3 * m0 + 0];
        float qya = q_coords[3 * m0 + 1];
        float qza = q_coords[3 * m0 + 2];
        int mq = (m1 < M) ? m1 : m0;
        float qxb = q_coords[3 * mq + 0];
        float qyb = q_coords[3 * mq + 1];
        float qzb = q_coords[3 * mq + 2];

        float xa = pa.x - qxa, ya = pa.y - qya; za = pa.z - qza;
        float xb = pb.x - qxb, yb = pb.y - qyb; zb = pb.z - qzb;
        x2a = xa * xa; y2a = ya * ya;
        x2b = xb * xb; y2b = yb * yb;
        float xy2a = x2a + y2a, xy2b = x2b + y2b;
        d2a = xy2a + za * za;
        d2b = xy2b + zb * zb;
        rxya = fast_sqrt(xy2a + EPS);
        rxyb = fast_sqrt(xy2b + EPS);
    }

    bool alive0 = (d2a <= 1.0f);
    bool alive1 = (d2b <= 1.0f) && (m1 < M);
    unsigned b0 = __ballot_sync(FULL, alive0);
    unsigned b1 = __ballot_sync(FULL, alive1);
    int n0 = __popc(b0);
    int n1 = __popc(b1);
    unsigned ltmask = (1u << lane) - 1u;

    // Warp-level compaction: survivor lane writes its data once (STS.128)
    if (alive0) s_surv[wid][0][__popc(b0 & ltmask)] = make_float4(x2a, y2a, za, rxya);
    if (alive1) s_surv[wid][1][__popc(b1 & ltmask)] = make_float4(x2b, y2b, zb, rxyb);
    __syncwarp();

    // Counted, warp-uniform survivor loop: one LDS.128 broadcast per survivor,
    // two independent FMA->MUFU chains for ILP.
    float acc0 = 0.0f, acc1 = 0.0f;
    int nmax = max(n0, n1);
    #pragma unroll 2
    for (int j = 0; j < nmax; j++) {
        if (j < n0) {
            float4 v = s_surv[wid][0][j];
            float dd = fmaf(-inc, v.z, v.w);
            float t = fmaf(cf.x, v.x,
                      fmaf(cf.y, v.y,
                      fmaf(cf.z, v.z * v.z, (cf.w * dd) * dd)));
            acc0 += __expf(t);
        }
        if (j < n1) {
            float4 v = s_surv[wid][1][j];
            float dd = fmaf(-inc, v.z, v.w);
            float t = fmaf(cf.x, v.x,
                      fmaf(cf.y, v.y,
                      fmaf(cf.z, v.z * v.z, (cf.w * dd) * dd)));
            acc1 += __expf(t);
        }
    }

    // Epilogue: full warp. Lanes 0-15 project query m0, lanes 16-31 query m1.
    s_acc[wid][0][lane] = acc0;
    s_acc[wid][1][lane] = acc1;
    __syncwarp();

    int qsel = lane >> 4;
    int o    = lane & 15;
    int m    = qsel ? m1 : m0;
    if (m < M) {
        const float* accp = s_acc[wid][qsel];
        float ot = 0.0f;
        #pragma unroll
        for (int j = 0; j < 32; j += 4) {
            float4 lam4 = *(const float4*)&s_lamT[o][j];
            float4 a4   = *(const float4*)&accp[j];
            ot = fmaf(a4.x, lam4.x,
                 fmaf(a4.y, lam4.y,
                 fmaf(a4.z, lam4.z,
                 fmaf(a4.w, lam4.w, ot))));
        }
        out[m * 16 + o] = ot;
    }
}

extern "C" void kernel_launch(void* const* d_in, const int* in_sizes, int n_in,
                              void* d_out, int out_size) {
    const float* points       = (const float*)d_in[0];
    const float* q_coords     = (const float*)d_in[1];
    const int*   support_idxs = (const int*)  d_in[2];
    const float* cy_radius    = (const float*)d_in[3];
    const float* disk_radius  = (const float*)d_in[4];
    const float* disk_width   = (const float*)d_in[5];
    const float* cone_radius  = (const float*)d_in[6];
    const float* cone_inc     = (const float*)d_in[7];
    const float* ellip_radii  = (const float*)d_in[8];
    const float* lambdas      = (const float*)d_in[9];
    float* out = (float*)d_out;

    int N = in_sizes[0] / 3;   // points has N*3 elements
    int M = in_sizes[1] / 3;   // q_coords has M*3 elements

    pack_points_kernel<<<(N + 255) / 256, 256>>>(points, N);

    int blocks = (M + Q_PER_BLOCK - 1) / Q_PER_BLOCK;
    gib_kernel<<<blocks, THREADS>>>(q_coords, support_idxs,
                                    cy_radius, disk_radius, disk_width,
                                    cone_radius, cone_inc, ellip_radii,
                                    lambdas, out, M);
}